// round 12
// baseline (speedup 1.0000x reference)
#include <cuda_runtime.h>

// Input:  x  (B=64, C=3, H=512, W+1=513) fp32; h_orig = x[b,0,0,512], w_orig = x[b,1,0,512]
// Output: (64, 3, 224, 224) fp32
// Resize shorter side to 256 (bilinear, half-pixel centers, rint), center-crop 224x224.
// R10: revert to R6 direct-gather base; 4 rows/thread for 48-LDG MLP,
// 41-reg cap (7 blocks/SM), all-int32 indexing.

#define OUT_H 224
#define OUT_W 224
#define IN_H 512
#define IN_W_STRIDE 513
#define PLANE (IN_H * IN_W_STRIDE)      // 262656 elements
#define RESIZE_TO 256.0f
#define ROWS_PER_BLK 4

__global__ __launch_bounds__(OUT_W, 7) void center_crop_kernel(
    const float* __restrict__ x, float* __restrict__ out)
{
    const int ygrp = blockIdx.x;    // 0..55
    const int b = blockIdx.y;       // 0..63
    const int tx = threadIdx.x;     // 0..223

    const float* img = x + b * (3 * PLANE);

    // per-image params
    const float h = img[IN_W_STRIDE - 1];
    const float w = img[PLANE + IN_W_STRIDE - 1];
    const float min_dim = fminf(h, w);
    const float scale = RESIZE_TO / min_dim;
    const float h_res = rintf(h * scale);
    const float w_res = rintf(w * scale);
    const float top  = rintf((h_res - (float)OUT_H) * 0.5f);
    const float left = rintf((w_res - (float)OUT_W) * 0.5f);

    const int hi = (int)h - 1;
    const int wi = (int)w - 1;

    // column coordinate — per thread, shared by all 4 rows
    float src_x = (((float)tx + left) + 0.5f) * w / w_res - 0.5f;
    src_x = fminf(fmaxf(src_x, 0.0f), w - 1.0f);
    const float x0f = floorf(src_x);
    const float wx = src_x - x0f;
    int x0 = (int)x0f;
    x0 = max(0, min(x0, wi));
    const int x1 = min(x0 + 1, wi);

    // row coordinates for the 4 rows (int32 offsets)
    int o00[ROWS_PER_BLK], o01[ROWS_PER_BLK], o10[ROWS_PER_BLK], o11[ROWS_PER_BLK];
    float wy[ROWS_PER_BLK];
    #pragma unroll
    for (int r = 0; r < ROWS_PER_BLK; r++) {
        const int y = ygrp * ROWS_PER_BLK + r;
        float src_y = (((float)y + top) + 0.5f) * h / h_res - 0.5f;
        src_y = fminf(fmaxf(src_y, 0.0f), h - 1.0f);
        const float y0f = floorf(src_y);
        wy[r] = src_y - y0f;
        int y0 = (int)y0f;
        y0 = max(0, min(y0, hi));
        const int y1 = min(y0 + 1, hi);
        o00[r] = y0 * IN_W_STRIDE + x0;
        o01[r] = y0 * IN_W_STRIDE + x1;
        o10[r] = y1 * IN_W_STRIDE + x0;
        o11[r] = y1 * IN_W_STRIDE + x1;
    }

    const int out_base = b * (3 * OUT_H * OUT_W)
                       + (ygrp * ROWS_PER_BLK) * OUT_W + tx;

    // batch all loads (channel stride is an LDG immediate), then compute.
    float v00[ROWS_PER_BLK][3], v01[ROWS_PER_BLK][3];
    float v10[ROWS_PER_BLK][3], v11[ROWS_PER_BLK][3];
    #pragma unroll
    for (int r = 0; r < ROWS_PER_BLK; r++) {
        #pragma unroll
        for (int c = 0; c < 3; c++) {
            v00[r][c] = __ldg(img + o00[r] + c * PLANE);
            v01[r][c] = __ldg(img + o01[r] + c * PLANE);
            v10[r][c] = __ldg(img + o10[r] + c * PLANE);
            v11[r][c] = __ldg(img + o11[r] + c * PLANE);
        }
    }

    #pragma unroll
    for (int c = 0; c < 3; c++) {
        #pragma unroll
        for (int r = 0; r < ROWS_PER_BLK; r++) {
            const float t0 = v00[r][c] + wx * (v01[r][c] - v00[r][c]);
            const float t1 = v10[r][c] + wx * (v11[r][c] - v10[r][c]);
            const float res = t0 + wy[r] * (t1 - t0);
            out[out_base + c * (OUT_H * OUT_W) + r * OUT_W] = res;
        }
    }
}

extern "C" void kernel_launch(void* const* d_in, const int* in_sizes, int n_in,
                              void* d_out, int out_size)
{
    const float* x = (const float*)d_in[0];
    float* out = (float*)d_out;
    dim3 grid(OUT_H / ROWS_PER_BLK, 64);
    dim3 block(OUT_W);
    center_crop_kernel<<<grid, block>>>(x, out);
}

// round 13
// speedup vs baseline: 1.9858x; 1.9858x over previous
#include <cuda_runtime.h>

// Input:  x  (B=64, C=3, H=512, W+1=513) fp32; h_orig = x[b,0,0,512], w_orig = x[b,1,0,512]
// Output: (64, 3, 224, 224) fp32
// Resize shorter side to 256 (bilinear, half-pixel centers, rint), center-crop 224x224.
// R12 = R6 base (2 rows/thread, 24-LDG MLP, int32 indexing)
//  + __launch_bounds__(224,9): 2016 thr/SM, reg budget 32 = R6's actual usage
//  + evict-first (streaming) output stores.

#define OUT_H 224
#define OUT_W 224
#define IN_H 512
#define IN_W_STRIDE 513
#define PLANE (IN_H * IN_W_STRIDE)      // 262656 elements, fits LDG imm offset
#define RESIZE_TO 256.0f
#define ROWS_PER_BLK 2

__global__ __launch_bounds__(OUT_W, 9) void center_crop_kernel(
    const float* __restrict__ x, float* __restrict__ out)
{
    const int ypair = blockIdx.x;   // 0..111
    const int b = blockIdx.y;       // 0..63
    const int tx = threadIdx.x;     // 0..223

    const float* img = x + b * (3 * PLANE);

    // per-image params
    const float h = img[IN_W_STRIDE - 1];
    const float w = img[PLANE + IN_W_STRIDE - 1];
    const float min_dim = fminf(h, w);
    const float scale = RESIZE_TO / min_dim;
    const float h_res = rintf(h * scale);
    const float w_res = rintf(w * scale);
    const float top  = rintf((h_res - (float)OUT_H) * 0.5f);
    const float left = rintf((w_res - (float)OUT_W) * 0.5f);

    const int hi = (int)h - 1;
    const int wi = (int)w - 1;

    // column coordinate — per thread, shared by both rows
    float src_x = (((float)tx + left) + 0.5f) * w / w_res - 0.5f;
    src_x = fminf(fmaxf(src_x, 0.0f), w - 1.0f);
    const float x0f = floorf(src_x);
    const float wx = src_x - x0f;
    int x0 = (int)x0f;
    x0 = max(0, min(x0, wi));
    const int x1 = min(x0 + 1, wi);

    // row coordinates for the 2 rows (int32 offsets)
    int off00[ROWS_PER_BLK], off01[ROWS_PER_BLK];
    int off10[ROWS_PER_BLK], off11[ROWS_PER_BLK];
    float wy[ROWS_PER_BLK];
    #pragma unroll
    for (int r = 0; r < ROWS_PER_BLK; r++) {
        const int y = ypair * ROWS_PER_BLK + r;
        float src_y = (((float)y + top) + 0.5f) * h / h_res - 0.5f;
        src_y = fminf(fmaxf(src_y, 0.0f), h - 1.0f);
        const float y0f = floorf(src_y);
        wy[r] = src_y - y0f;
        int y0 = (int)y0f;
        y0 = max(0, min(y0, hi));
        const int y1 = min(y0 + 1, hi);
        off00[r] = y0 * IN_W_STRIDE + x0;
        off01[r] = y0 * IN_W_STRIDE + x1;
        off10[r] = y1 * IN_W_STRIDE + x0;
        off11[r] = y1 * IN_W_STRIDE + x1;
    }

    // batch ALL 24 loads first, then compute (channel stride = LDG immediate)
    float v00[ROWS_PER_BLK][3], v01[ROWS_PER_BLK][3];
    float v10[ROWS_PER_BLK][3], v11[ROWS_PER_BLK][3];
    #pragma unroll
    for (int r = 0; r < ROWS_PER_BLK; r++) {
        #pragma unroll
        for (int c = 0; c < 3; c++) {
            v00[r][c] = __ldg(img + off00[r] + c * PLANE);
            v01[r][c] = __ldg(img + off01[r] + c * PLANE);
            v10[r][c] = __ldg(img + off10[r] + c * PLANE);
            v11[r][c] = __ldg(img + off11[r] + c * PLANE);
        }
    }

    const int out_base = b * (3 * OUT_H * OUT_W)
                       + (ypair * ROWS_PER_BLK) * OUT_W + tx;
    #pragma unroll
    for (int c = 0; c < 3; c++) {
        #pragma unroll
        for (int r = 0; r < ROWS_PER_BLK; r++) {
            const float t0 = v00[r][c] + wx * (v01[r][c] - v00[r][c]);
            const float t1 = v10[r][c] + wx * (v11[r][c] - v10[r][c]);
            const float res = t0 + wy[r] * (t1 - t0);
            __stcs(out + out_base + c * (OUT_H * OUT_W) + r * OUT_W, res);
        }
    }
}

extern "C" void kernel_launch(void* const* d_in, const int* in_sizes, int n_in,
                              void* d_out, int out_size)
{
    const float* x = (const float*)d_in[0];
    float* out = (float*)d_out;
    dim3 grid(OUT_H / ROWS_PER_BLK, 64);
    dim3 block(OUT_W);
    center_crop_kernel<<<grid, block>>>(x, out);
}